// round 14
// baseline (speedup 1.0000x reference)
#include <cuda_runtime.h>

// EMD / min-permutation matching on GB300.
//   B=32768, N=6, D=64.
//   cost[b] = (sum sq norms) - 2 * maxAssign(G),  G[n][m] = p_n . t_m
//   out[0] = sum_b cost[b]
//
// R14 = persistent R6. 740 CTAs (5/SM), each loops over 16-batch tiles.
// While the 16 DP threads run the assignment tail for tile k, the other 112
// threads prefetch tile k+1's pred slices -> the DP tail overlaps memory
// instead of draining the pipe. Also removes wave quantization (2.77 waves).

#define BLOCK   128
#define TPB     16    // batches per tile (BLOCK/8)
#define SLOT    44    // 36 G + 1 sq + 7 pad; 44 % 32 == 12 -> conflict-free

__global__ __launch_bounds__(BLOCK, 5)
void emd_kernel(const float* __restrict__ preds,
                const float* __restrict__ targets,
                float* __restrict__ out, int B, int ntiles)
{
    __shared__ float sh[BLOCK * SLOT];    // 22528 B

    const int t  = threadIdx.x;
    const int bb = t >> 3;                // batch within tile
    const int j  = t & 7;                 // lane within 8-thread group

    float cost = 0.0f;

    // ---- prologue: prefetch first tile's pred slices
    float4 pa[6], pc[6];
    {
        const int b0 = blockIdx.x * TPB + bb;
        const int b  = (b0 < B) ? b0 : (B - 1);
        const float* pp = preds + (size_t)b * 384 + 4 * j;
#pragma unroll
        for (int n = 0; n < 6; ++n) {
            pa[n] = *(const float4*)(pp + n * 64);
            pc[n] = *(const float4*)(pp + n * 64 + 32);
        }
    }

    for (int tile = blockIdx.x; tile < ntiles; tile += gridDim.x) {
        const int bB = tile * TPB + bb;
        const int b  = (bB < B) ? bB : (B - 1);
        const float* tt = targets + (size_t)b * 384 + 4 * j;

        // ---- squared p norms (p already in registers)
        float sq = 0.0f;
#pragma unroll
        for (int n = 0; n < 6; ++n) {
            sq += pa[n].x*pa[n].x + pa[n].y*pa[n].y + pa[n].z*pa[n].z + pa[n].w*pa[n].w;
            sq += pc[n].x*pc[n].x + pc[n].y*pc[n].y + pc[n].z*pc[n].z + pc[n].w*pc[n].w;
        }

        // ---- stream target rows, accumulate Gram + sq
        float G[36];
#pragma unroll
        for (int m = 0; m < 6; ++m) {
            float4 qa = *(const float4*)(tt + m * 64);
            float4 qc = *(const float4*)(tt + m * 64 + 32);
            sq += qa.x*qa.x + qa.y*qa.y + qa.z*qa.z + qa.w*qa.w;
            sq += qc.x*qc.x + qc.y*qc.y + qc.z*qc.z + qc.w*qc.w;
#pragma unroll
            for (int n = 0; n < 6; ++n) {
                G[n * 6 + m] = pa[n].x*qa.x + pa[n].y*qa.y + pa[n].z*qa.z + pa[n].w*qa.w
                             + pc[n].x*qc.x + pc[n].y*qc.y + pc[n].z*qc.z + pc[n].w*qc.w;
            }
        }

        // ---- write partial (G, sq); STS.128, conflict-free
        {
            float* slot = &sh[t * SLOT];
#pragma unroll
            for (int i = 0; i < 9; ++i)
                *(float4*)&slot[4 * i] =
                    make_float4(G[4*i], G[4*i+1], G[4*i+2], G[4*i+3]);
            slot[36] = sq;
        }
        __syncthreads();

        const int ntile = tile + gridDim.x;

        // ---- 112 non-DP threads: prefetch next tile's p NOW (overlaps DP tail)
        if (t >= TPB && ntile < ntiles) {
            const int nb0 = ntile * TPB + bb;
            const int nb  = (nb0 < B) ? nb0 : (B - 1);
            const float* pp = preds + (size_t)nb * 384 + 4 * j;
#pragma unroll
            for (int n = 0; n < 6; ++n) {
                pa[n] = *(const float4*)(pp + n * 64);
                pc[n] = *(const float4*)(pp + n * 64 + 32);
            }
        }

        // ---- 16 DP threads: sum 8 partials, run subset DP
        if (t < TPB) {
            const int bOut = tile * TPB + t;
            float A[37];
            {   // seed from first rotated slot
                const int rot0 = t & 7;
                const float* s0 = &sh[(t * 8 + rot0) * SLOT];
#pragma unroll
                for (int e = 0; e < 9; ++e) {
                    float4 v = *(const float4*)&s0[4 * e];
                    A[4*e]   = v.x;  A[4*e+1] = v.y;
                    A[4*e+2] = v.z;  A[4*e+3] = v.w;
                }
                A[36] = s0[36];
            }
#pragma unroll
            for (int l = 1; l < 8; ++l) {
                const int rot = (l + t) & 7;
                const float* s1 = &sh[(t * 8 + rot) * SLOT];
#pragma unroll
                for (int e = 0; e < 9; ++e) {
                    float4 v = *(const float4*)&s1[4 * e];
                    A[4*e]   += v.x;  A[4*e+1] += v.y;
                    A[4*e+2] += v.z;  A[4*e+3] += v.w;
                }
                A[36] += s1[36];
            }

            if (bOut < B) {
                float dp[64];
                dp[0] = 0.0f;
#pragma unroll
                for (int k = 1; k <= 6; ++k) {
                    const int r = k - 1;
#pragma unroll
                    for (int S = 1; S < 64; ++S) {
                        if (__popc((unsigned)S) == k) {
                            float best = -3.0e38f;
#pragma unroll
                            for (int m = 0; m < 6; ++m)
                                if (S & (1 << m))
                                    best = fmaxf(best, dp[S ^ (1 << m)] + A[r * 6 + m]);
                            dp[S] = best;
                        }
                    }
                }
                cost += A[36] - 2.0f * dp[63];
            }
        }
        __syncthreads();     // partial reads done before smem reuse

        // ---- DP threads load their next-tile p after the tail
        if (t < TPB && ntile < ntiles) {
            const int nb0 = ntile * TPB + bb;
            const int nb  = (nb0 < B) ? nb0 : (B - 1);
            const float* pp = preds + (size_t)nb * 384 + 4 * j;
#pragma unroll
            for (int n = 0; n < 6; ++n) {
                pa[n] = *(const float4*)(pp + n * 64);
                pc[n] = *(const float4*)(pp + n * 64 + 32);
            }
        }
    }

    // ---- one atomicAdd per CTA (cost lives on t<16)
    if (t < 32) {
#pragma unroll
        for (int o = 8; o > 0; o >>= 1)
            cost += __shfl_down_sync(0xffffffffu, cost, o);
        if (t == 0) atomicAdd(out, cost);
    }
}

extern "C" void kernel_launch(void* const* d_in, const int* in_sizes, int n_in,
                              void* d_out, int out_size)
{
    const float* preds   = (const float*)d_in[0];
    const float* targets = (const float*)d_in[1];
    const int B = in_sizes[0] / 384;           // 6 * 64 floats per batch
    const int ntiles = (B + TPB - 1) / TPB;

    cudaMemsetAsync(d_out, 0, sizeof(float));
    int grid = 5 * 148;                        // persistent: 5 CTAs per SM
    if (grid > ntiles) grid = ntiles;
    emd_kernel<<<grid, BLOCK>>>(preds, targets, (float*)d_out, B, ntiles);
}

// round 16
// speedup vs baseline: 1.1054x; 1.1054x over previous
#include <cuda_runtime.h>

// EMD / min-permutation matching on GB300.
//   B=32768, N=6, D=64.
//   cost[b] = (sum sq norms) - 2 * maxAssign(G),  G[n][m] = p_n . t_m
//   out[0] = sum_b cost[b]
//
// R15 (resubmit — previous run hit a transient "device busy" infra fault):
// R6 + one shfl_xor(4) pre-reduction round after the Gram phase:
// partials per batch drop 8 -> 4 before the smem re-partition, halving the
// STS traffic, the barrier-tail gather (36 LDS.128 instead of 72) and the
// smem footprint (11.3 KB). Loads/Gram/DP/launch identical to R6 (best).

#define BLOCK   128
#define SLOT    44    // 36 G + 1 sq + 7 pad; s*44%32 distinct per 8-lane phase

__global__ __launch_bounds__(BLOCK, 5)
void emd_kernel(const float* __restrict__ preds,
                const float* __restrict__ targets,
                float* __restrict__ out, int B)
{
    __shared__ float sh[(BLOCK / 2) * SLOT];   // 64 slots = 11264 B

    const int t    = threadIdx.x;
    const int g    = blockIdx.x * BLOCK + t;
    const int bRaw = g >> 3;          // batch index
    const int j    = g & 7;           // lane within 8-thread group
    const int bb   = t >> 3;          // batch within CTA (0..15)
    const int b = (bRaw < B) ? bRaw : (B - 1);   // clamp keeps lanes converged

    const float* pp = preds   + (size_t)b * 384 + 4 * j;
    const float* tt = targets + (size_t)b * 384 + 4 * j;

    // ---- 1) 12 pred loads front-batched (register resident)
    float4 pa[6], pc[6];
#pragma unroll
    for (int n = 0; n < 6; ++n) {
        pa[n] = *(const float4*)(pp + n * 64);
        pc[n] = *(const float4*)(pp + n * 64 + 32);
    }

    float sq = 0.0f;
#pragma unroll
    for (int n = 0; n < 6; ++n) {
        sq += pa[n].x*pa[n].x + pa[n].y*pa[n].y + pa[n].z*pa[n].z + pa[n].w*pa[n].w;
        sq += pc[n].x*pc[n].x + pc[n].y*pc[n].y + pc[n].z*pc[n].z + pc[n].w*pc[n].w;
    }

    float G[36];

    // ---- 2) stream target rows, accumulate partial Gram + sq (R6 schedule)
#pragma unroll
    for (int m = 0; m < 6; ++m) {
        float4 qa = *(const float4*)(tt + m * 64);
        float4 qc = *(const float4*)(tt + m * 64 + 32);
        sq += qa.x*qa.x + qa.y*qa.y + qa.z*qa.z + qa.w*qa.w;
        sq += qc.x*qc.x + qc.y*qc.y + qc.z*qc.z + qc.w*qc.w;
#pragma unroll
        for (int n = 0; n < 6; ++n) {
            G[n * 6 + m] = pa[n].x*qa.x + pa[n].y*qa.y + pa[n].z*qa.z + pa[n].w*qa.w
                         + pc[n].x*qc.x + pc[n].y*qc.y + pc[n].z*qc.z + pc[n].w*qc.w;
        }
    }

    // ---- 3) one butterfly round: lanes j and j^4 combine -> 4 partials/batch
#pragma unroll
    for (int i = 0; i < 36; ++i)
        G[i] += __shfl_xor_sync(0xffffffffu, G[i], 4);
    sq += __shfl_xor_sync(0xffffffffu, sq, 4);

    // ---- 4) lanes j<4 write their combined partial; STS.128 conflict-free
    if (j < 4) {
        float* slot = &sh[(bb * 4 + j) * SLOT];
#pragma unroll
        for (int i = 0; i < 9; ++i)
            *(float4*)&slot[4 * i] = make_float4(G[4*i], G[4*i+1], G[4*i+2], G[4*i+3]);
        slot[36] = sq;
    }
    __syncthreads();

    // ---- 5) one thread per batch: sum 4 partials, run DP
    float cost = 0.0f;
    if (t < BLOCK / 8) {                         // 16 batches per CTA
        const int bOut = blockIdx.x * (BLOCK / 8) + t;
        float A[37];

        {   // seed from first rotated slot
            const int rot0 = t & 3;
            const float* s0 = &sh[(t * 4 + rot0) * SLOT];
#pragma unroll
            for (int e = 0; e < 9; ++e) {
                float4 v = *(const float4*)&s0[4 * e];
                A[4*e]   = v.x;  A[4*e+1] = v.y;
                A[4*e+2] = v.z;  A[4*e+3] = v.w;
            }
            A[36] = s0[36];
        }
#pragma unroll
        for (int l = 1; l < 4; ++l) {
            const int rot = (l + t) & 3;                 // de-conflict rotation
            const float* s1 = &sh[(t * 4 + rot) * SLOT];
#pragma unroll
            for (int e = 0; e < 9; ++e) {
                float4 v = *(const float4*)&s1[4 * e];
                A[4*e]   += v.x;  A[4*e+1] += v.y;
                A[4*e+2] += v.z;  A[4*e+3] += v.w;
            }
            A[36] += s1[36];
        }

        if (bOut < B) {
            float dp[64];
            dp[0] = 0.0f;
#pragma unroll
            for (int k = 1; k <= 6; ++k) {
                const int r = k - 1;
#pragma unroll
                for (int S = 1; S < 64; ++S) {
                    if (__popc((unsigned)S) == k) {
                        float best = -3.0e38f;
#pragma unroll
                        for (int m = 0; m < 6; ++m)
                            if (S & (1 << m))
                                best = fmaxf(best, dp[S ^ (1 << m)] + A[r * 6 + m]);
                        dp[S] = best;
                    }
                }
            }
            cost = A[36] - 2.0f * dp[63];
        }
    }

    // ---- 6) reduce the 16 costs (first warp) and atomicAdd once
    if (t < 32) {
#pragma unroll
        for (int o = 8; o > 0; o >>= 1)
            cost += __shfl_down_sync(0xffffffffu, cost, o);
        if (t == 0) atomicAdd(out, cost);
    }
}

extern "C" void kernel_launch(void* const* d_in, const int* in_sizes, int n_in,
                              void* d_out, int out_size)
{
    const float* preds   = (const float*)d_in[0];
    const float* targets = (const float*)d_in[1];
    const int B = in_sizes[0] / 384;   // 6 * 64 floats per batch

    cudaMemsetAsync(d_out, 0, sizeof(float));
    const long long threads = (long long)B * 8;
    const int grid = (int)((threads + BLOCK - 1) / BLOCK);
    emd_kernel<<<grid, BLOCK>>>(preds, targets, (float*)d_out, B);
}

// round 17
// speedup vs baseline: 1.1133x; 1.0071x over previous
#include <cuda_runtime.h>

// EMD / min-permutation matching on GB300 — FINAL (R6, best measured: 16.4us).
//   B=32768, N=6, D=64.
//   cost[b] = (sum sq norms) - 2 * maxAssign(G),  G[n][m] = p_n . t_m
//   out[0] = sum_b cost[b]
//
// Structure: 8 lanes/batch (lane j owns dims [4j,4j+4) U [32+4j,32+4j+4));
// 12 pred LDG.128 front-batched, 12 target LDG.128 streamed through the Gram
// accumulation; partial (G,sq) re-partitioned via smem (stride 44 floats,
// conflict-free STS/LDS.128); one thread per batch sums 8 partials and runs
// the 64-state Held-Karp assignment DP; one atomicAdd per CTA.
// Measured plateau: ~6.1 TB/s effective HBM (~76% of spec), DRAM duty 63%.

#define BLOCK   128
#define SLOT    44    // floats per partial slot: 36 G + 1 sq + 7 pad
                      // 44 % 32 == 12 -> STS.128 conflict-free per 8-lane phase

__global__ __launch_bounds__(BLOCK, 5)
void emd_kernel(const float* __restrict__ preds,
                const float* __restrict__ targets,
                float* __restrict__ out, int B)
{
    __shared__ float sh[BLOCK * SLOT];    // 22528 B

    const int t    = threadIdx.x;
    const int g    = blockIdx.x * BLOCK + t;
    const int bRaw = g >> 3;          // batch index
    const int j    = g & 7;           // lane within 8-thread group
    const int b = (bRaw < B) ? bRaw : (B - 1);   // clamp keeps lanes converged

    const float* pp = preds   + (size_t)b * 384 + 4 * j;
    const float* tt = targets + (size_t)b * 384 + 4 * j;

    // ---- 1) 12 pred loads front-batched (register resident)
    float4 pa[6], pc[6];
#pragma unroll
    for (int n = 0; n < 6; ++n) {
        pa[n] = *(const float4*)(pp + n * 64);
        pc[n] = *(const float4*)(pp + n * 64 + 32);
    }

    float sq = 0.0f;
#pragma unroll
    for (int n = 0; n < 6; ++n) {
        sq += pa[n].x*pa[n].x + pa[n].y*pa[n].y + pa[n].z*pa[n].z + pa[n].w*pa[n].w;
        sq += pc[n].x*pc[n].x + pc[n].y*pc[n].y + pc[n].z*pc[n].z + pc[n].w*pc[n].w;
    }

    float G[36];
#pragma unroll
    for (int i = 0; i < 36; ++i) G[i] = 0.0f;

    // ---- 2) stream target rows, accumulate partial Gram + sq
#pragma unroll
    for (int m = 0; m < 6; ++m) {
        float4 qa = *(const float4*)(tt + m * 64);
        float4 qc = *(const float4*)(tt + m * 64 + 32);
        sq += qa.x*qa.x + qa.y*qa.y + qa.z*qa.z + qa.w*qa.w;
        sq += qc.x*qc.x + qc.y*qc.y + qc.z*qc.z + qc.w*qc.w;
#pragma unroll
        for (int n = 0; n < 6; ++n) {
            G[n * 6 + m] += pa[n].x*qa.x + pa[n].y*qa.y + pa[n].z*qa.z + pa[n].w*qa.w
                          + pc[n].x*qc.x + pc[n].y*qc.y + pc[n].z*qc.z + pc[n].w*qc.w;
        }
    }

    // ---- 3) write partial (G, sq) to own slot; STS.128, conflict-free
    {
        float* slot = &sh[t * SLOT];
#pragma unroll
        for (int i = 0; i < 9; ++i)
            *(float4*)&slot[4 * i] = make_float4(G[4*i], G[4*i+1], G[4*i+2], G[4*i+3]);
        slot[36] = sq;
    }
    __syncthreads();

    // ---- 4) one thread per batch: sum 8 partials, run DP
    float cost = 0.0f;
    if (t < BLOCK / 8) {                         // 16 batches per CTA
        const int bOut = blockIdx.x * (BLOCK / 8) + t;
        float A[37];
#pragma unroll
        for (int i = 0; i < 37; ++i) A[i] = 0.0f;

#pragma unroll
        for (int l = 0; l < 8; ++l) {
            const int rot = (l + t) & 7;                 // de-conflict rotation
            const float* slot = &sh[(t * 8 + rot) * SLOT];
#pragma unroll
            for (int e = 0; e < 9; ++e) {
                float4 v = *(const float4*)&slot[4 * e];
                A[4*e]   += v.x;  A[4*e+1] += v.y;
                A[4*e+2] += v.z;  A[4*e+3] += v.w;
            }
            A[36] += slot[36];
        }

        if (bOut < B) {
            float dp[64];
            dp[0] = 0.0f;
#pragma unroll
            for (int k = 1; k <= 6; ++k) {
                const int r = k - 1;
#pragma unroll
                for (int S = 1; S < 64; ++S) {
                    if (__popc((unsigned)S) == k) {
                        float best = -3.0e38f;
#pragma unroll
                        for (int m = 0; m < 6; ++m)
                            if (S & (1 << m))
                                best = fmaxf(best, dp[S ^ (1 << m)] + A[r * 6 + m]);
                        dp[S] = best;
                    }
                }
            }
            cost = A[36] - 2.0f * dp[63];
        }
    }

    // ---- 5) reduce the 16 costs (first warp) and atomicAdd once
    if (t < 32) {
#pragma unroll
        for (int o = 8; o > 0; o >>= 1)
            cost += __shfl_down_sync(0xffffffffu, cost, o);
        if (t == 0) atomicAdd(out, cost);
    }
}

extern "C" void kernel_launch(void* const* d_in, const int* in_sizes, int n_in,
                              void* d_out, int out_size)
{
    const float* preds   = (const float*)d_in[0];
    const float* targets = (const float*)d_in[1];
    const int B = in_sizes[0] / 384;   // 6 * 64 floats per batch

    cudaMemsetAsync(d_out, 0, sizeof(float));
    const long long threads = (long long)B * 8;
    const int grid = (int)((threads + BLOCK - 1) / BLOCK);
    emd_kernel<<<grid, BLOCK>>>(preds, targets, (float*)d_out, B);
}